// round 2
// baseline (speedup 1.0000x reference)
#include <cuda_runtime.h>
#include <cstdint>

#define K_DIM      128
#define O_DIM      128
#define CHUNK      64          // rows of x per pipeline stage
#define THREADS    256         // 8 warps: 4 o-groups x 2 m-groups
#define LDS_STRIDE 132         // 128 + 4 padding -> conflict-free frag loads
#define NBUF       6           // cp.async pipeline depth (5 chunks in flight)
#define BUF_FLOATS (CHUNK * LDS_STRIDE)
#define SMEM_FLOATS (NBUF * BUF_FLOATS)
#define SMEM_BYTES  (SMEM_FLOATS * 4)
// W (128x132 floats = 67584 B) is staged overlapping buffers 2..3; it is dead
// once B fragments are register-resident, after which bufs 2..3 join the ring.
#define WS_OFFSET  (2 * BUF_FLOATS)

__device__ __forceinline__ uint32_t cvt_tf32(float f) {
    uint32_t r;
    asm("cvt.rna.tf32.f32 %0, %1;" : "=r"(r) : "f"(f));
    return r;
}
__device__ __forceinline__ void cp_async16(uint32_t smem_addr, const void* gptr) {
    asm volatile("cp.async.cg.shared.global [%0], [%1], 16;" :: "r"(smem_addr), "l"(gptr));
}
__device__ __forceinline__ void cp_commit() {
    asm volatile("cp.async.commit_group;");
}

__global__ void __launch_bounds__(THREADS, 1)
qlinear_tf32_kernel(const float* __restrict__ x,
                    const float* __restrict__ W,
                    float* __restrict__ out,
                    int nrows, int nchunks)
{
    extern __shared__ float smem[];
    float* ws = smem + WS_OFFSET;                   // [128][132] W (o,k) — prologue only

    const int tid = threadIdx.x;
    const uint32_t smem_a = (uint32_t)__cvta_generic_to_shared(smem);
    const uint32_t ws_a   = smem_a + WS_OFFSET * 4;

    // ---- stage W (coalesced float4, row-major, padded) ----
    #pragma unroll
    for (int j = 0; j < 16; j++) {
        int flat = tid + j * THREADS;               // 0..4095 float4s
        int o  = flat >> 5;
        int c4 = flat & 31;
        cp_async16(ws_a + (uint32_t)(o * LDS_STRIDE + c4 * 4) * 4,
                   W + o * K_DIM + c4 * 4);
    }
    cp_commit();                                    // G_W

    // ---- chunk staging: loads guarded, commit done by caller ----
    auto stage = [&](int chunk, int buf) {
        if (chunk < nchunks) {
            int row0 = chunk * CHUNK;
            uint32_t base = smem_a + (uint32_t)(buf * BUF_FLOATS) * 4;
            #pragma unroll
            for (int j = 0; j < 8; j++) {
                int flat = tid + j * THREADS;       // 0..2047 float4s
                int r  = flat >> 5;                 // 0..63
                int c4 = flat & 31;
                int gr = row0 + r;
                if (gr >= nrows) gr = nrows - 1;    // clamp: never OOB, data unused
                cp_async16(base + (uint32_t)(r * LDS_STRIDE + c4 * 4) * 4,
                           x + (size_t)gr * K_DIM + c4 * 4);
            }
        }
    };

    const int c0 = blockIdx.x;
    const int g  = gridDim.x;

    // buffers 0,1 do not overlap the W region — stage them before reading W
    stage(c0 + 0 * g, 0); cp_commit();
    stage(c0 + 1 * g, 1); cp_commit();
    asm volatile("cp.async.wait_group 2;");         // G_W retired (bufs 0,1 may pend)
    __syncthreads();

    // ---- per-warp geometry ----
    const int lane = tid & 31, wid = tid >> 5;
    const int q = lane >> 2;        // groupID (0..7)
    const int t = lane & 3;         // threadID in group (0..3)
    const int wo = wid & 3;         // o-group: cols [wo*32, wo*32+32)
    const int wm = wid >> 2;        // m-group: rows [wm*32, wm*32+32) of chunk

    // ---- B fragments: warp's entire W slice, register-resident ----
    // B element (k, n) = W[n][k]; n = wo*32 + tt*8 + q; b0: k=8s+t, b1: k=8s+t+4
    uint32_t Bf[16][4][2];
    #pragma unroll
    for (int s = 0; s < 16; s++)
        #pragma unroll
        for (int tt = 0; tt < 4; tt++) {
            const float* p = ws + (wo * 32 + tt * 8 + q) * LDS_STRIDE + s * 8 + t;
            Bf[s][tt][0] = cvt_tf32(p[0]);
            Bf[s][tt][1] = cvt_tf32(p[4]);
        }
    __syncthreads();                                // all warps done with W region

    // now bufs 2..5 (incl. former W region) join the ring
    stage(c0 + 2 * g, 2); cp_commit();
    stage(c0 + 3 * g, 3); cp_commit();
    stage(c0 + 4 * g, 4); cp_commit();
    stage(c0 + 5 * g, 5); cp_commit();

    // ---- main pipeline: one wait + one commit per iteration, NBUF-deep ring ----
    int buf = 0;
    for (int c = c0; c < nchunks; c += g) {
        asm volatile("cp.async.wait_group %0;" :: "n"(NBUF - 1)); // oldest group done
        __syncthreads();                            // its data visible to all warps

        const float* xb = smem + buf * BUF_FLOATS;

        #pragma unroll
        for (int mt = 0; mt < 2; mt++) {
            const int mrow = wm * 32 + mt * 16;
            float acc[4][4];
            #pragma unroll
            for (int tt = 0; tt < 4; tt++)
                #pragma unroll
                for (int e = 0; e < 4; e++) acc[tt][e] = 0.0f;

            #pragma unroll
            for (int s = 0; s < 16; s++) {
                const float* a0p = xb + (mrow + q) * LDS_STRIDE + s * 8 + t;
                const float* a1p = a0p + 8 * LDS_STRIDE;
                uint32_t a0 = cvt_tf32(a0p[0]);
                uint32_t a2 = cvt_tf32(a0p[4]);
                uint32_t a1 = cvt_tf32(a1p[0]);
                uint32_t a3 = cvt_tf32(a1p[4]);
                #pragma unroll
                for (int tt = 0; tt < 4; tt++) {
                    asm volatile(
                        "mma.sync.aligned.m16n8k8.row.col.f32.tf32.tf32.f32 "
                        "{%0,%1,%2,%3}, {%4,%5,%6,%7}, {%8,%9}, {%0,%1,%2,%3};"
                        : "+f"(acc[tt][0]), "+f"(acc[tt][1]),
                          "+f"(acc[tt][2]), "+f"(acc[tt][3])
                        : "r"(a0), "r"(a1), "r"(a2), "r"(a3),
                          "r"(Bf[s][tt][0]), "r"(Bf[s][tt][1]));
                }
            }

            // epilogue: C frags -> gmem, 8B sector-aligned float2 stores
            const int r1 = c * CHUNK + mrow + q;
            const int r2 = r1 + 8;
            #pragma unroll
            for (int tt = 0; tt < 4; tt++) {
                const int col = wo * 32 + tt * 8 + 2 * t;
                if (r1 < nrows)
                    *reinterpret_cast<float2*>(out + (size_t)r1 * O_DIM + col) =
                        make_float2(acc[tt][0], acc[tt][1]);
                if (r2 < nrows)
                    *reinterpret_cast<float2*>(out + (size_t)r2 * O_DIM + col) =
                        make_float2(acc[tt][2], acc[tt][3]);
            }
        }

        __syncthreads();                            // all warps done with this buffer
        stage(c + NBUF * g, buf);                   // refill the slot just consumed
        cp_commit();                                // (possibly-empty group keeps count uniform)

        if (++buf == NBUF) buf = 0;
    }
}

extern "C" void kernel_launch(void* const* d_in, const int* in_sizes, int n_in,
                              void* d_out, int out_size)
{
    const float* x = (const float*)d_in[0];
    const float* W = (const float*)d_in[1];
    float* out = (float*)d_out;

    const int nrows   = in_sizes[0] / K_DIM;
    const int nchunks = (nrows + CHUNK - 1) / CHUNK;

    cudaFuncSetAttribute(qlinear_tf32_kernel,
                         cudaFuncAttributeMaxDynamicSharedMemorySize, SMEM_BYTES);

    int sms = 148;
    cudaDeviceGetAttribute(&sms, cudaDevAttrMultiProcessorCount, 0);
    int grid = sms;
    if (grid > nchunks) grid = nchunks;
    if (grid < 1) grid = 1;

    qlinear_tf32_kernel<<<grid, THREADS, SMEM_BYTES>>>(x, W, out, nrows, nchunks);
}

// round 4
// speedup vs baseline: 1.1290x; 1.1290x over previous
#include <cuda_runtime.h>
#include <cstdint>

#define K_DIM      128
#define O_DIM      128
#define CHUNK      64          // rows of x per pipeline stage
#define THREADS    256         // 8 warps: 4 o-groups x 2 m-groups
#define LDS_STRIDE 132         // 128 + 4 padding -> conflict-free frag loads
#define NBUF       4           // ring depth (3 chunks in flight)
#define BUF_FLOATS (CHUNK * LDS_STRIDE)
#define SMEM_FLOATS (NBUF * BUF_FLOATS)
#define SMEM_BYTES  (SMEM_FLOATS * 4)
// W (128x132 floats = 67584 B = exactly 2 buffers) overlays bufs 2..3 during
// the prologue; dead once B fragments are register-resident.
#define WS_OFFSET  (2 * BUF_FLOATS)

// x is fed to the tf32 MMA as raw fp32 bits (HW truncates to tf32).
// Mean relative shrink of truncation = 2^-11 * ln2 = 3.38e-4; compensate on W.
#define W_SCALE 1.000338f

__device__ __forceinline__ uint32_t cvt_tf32(float f) {
    uint32_t r;
    asm("cvt.rna.tf32.f32 %0, %1;" : "=r"(r) : "f"(f));
    return r;
}
__device__ __forceinline__ void cp_async16(uint32_t smem_addr, const void* gptr) {
    asm volatile("cp.async.cg.shared.global [%0], [%1], 16;" :: "r"(smem_addr), "l"(gptr));
}
__device__ __forceinline__ void cp_commit() {
    asm volatile("cp.async.commit_group;");
}

__global__ void __launch_bounds__(THREADS, 1)
qlinear_tf32_kernel(const float* __restrict__ x,
                    const float* __restrict__ W,
                    float* __restrict__ out,
                    int nrows, int nchunks)
{
    extern __shared__ float smem[];
    float* ws = smem + WS_OFFSET;                   // [128][132] W (o,k) — prologue only

    const int tid = threadIdx.x;
    const uint32_t smem_a = (uint32_t)__cvta_generic_to_shared(smem);
    const uint32_t ws_a   = smem_a + WS_OFFSET * 4;

    // ---- stage W (coalesced float4, row-major, padded) ----
    #pragma unroll
    for (int j = 0; j < 16; j++) {
        int flat = tid + j * THREADS;               // 0..4095 float4s
        int o  = flat >> 5;
        int c4 = flat & 31;
        cp_async16(ws_a + (uint32_t)(o * LDS_STRIDE + c4 * 4) * 4,
                   W + o * K_DIM + c4 * 4);
    }
    cp_commit();                                    // G_W

    auto stage = [&](int chunk, int buf) {
        if (chunk < nchunks) {
            int row0 = chunk * CHUNK;
            uint32_t base = smem_a + (uint32_t)(buf * BUF_FLOATS) * 4;
            #pragma unroll
            for (int j = 0; j < 8; j++) {
                int flat = tid + j * THREADS;       // 0..2047 float4s
                int r  = flat >> 5;                 // 0..63
                int c4 = flat & 31;
                int gr = row0 + r;
                if (gr >= nrows) gr = nrows - 1;    // clamp: never OOB, data unused
                cp_async16(base + (uint32_t)(r * LDS_STRIDE + c4 * 4) * 4,
                           x + (size_t)gr * K_DIM + c4 * 4);
            }
        }
    };

    const int c0 = blockIdx.x;
    const int g  = gridDim.x;

    // bufs 0,1 don't overlap W — stage them before reading W
    stage(c0 + 0 * g, 0); cp_commit();
    stage(c0 + 1 * g, 1); cp_commit();
    asm volatile("cp.async.wait_group 2;");         // W retired (b0,b1 may pend)
    __syncthreads();

    // ---- per-warp geometry ----
    const int lane = tid & 31, wid = tid >> 5;
    const int q = lane >> 2;        // groupID (0..7)
    const int t = lane & 3;         // threadID in group (0..3)
    const int wo = wid & 3;         // o-group: cols [wo*32, wo*32+32)
    const int wm = wid >> 2;        // m-group: rows [wm*32, wm*32+32) of chunk

    // ---- B fragments: warp's W slice, register-resident (rna + compensation) ----
    uint32_t Bf[16][4][2];
    #pragma unroll
    for (int s = 0; s < 16; s++)
        #pragma unroll
        for (int tt = 0; tt < 4; tt++) {
            const float* p = ws + (wo * 32 + tt * 8 + q) * LDS_STRIDE + s * 8 + t;
            Bf[s][tt][0] = cvt_tf32(p[0] * W_SCALE);
            Bf[s][tt][1] = cvt_tf32(p[4] * W_SCALE);
        }
    __syncthreads();                                // all warps done with W region

    stage(c0 + 2 * g, 2); cp_commit();              // pending: b0,b1,b2

    // ---- main pipeline: wait + single sync + restage + compute per chunk ----
    int idx = 0;
    for (int c = c0; c < nchunks; c += g, idx++) {
        const int buf = idx & (NBUF - 1);
        asm volatile("cp.async.wait_group 2;");     // this chunk's buffer arrived
        __syncthreads();                            // visible to all; buf(idx-1) fully drained

        // restage the buffer consumed LAST iteration ((buf+3)&3): safe post-barrier
        stage(c + 3 * g, (buf + 3) & (NBUF - 1));
        cp_commit();

        const uint32_t* xb = reinterpret_cast<const uint32_t*>(smem)
                           + buf * BUF_FLOATS + (wm * 32 + q) * LDS_STRIDE + t;

        float acc[2][4][4];
        #pragma unroll
        for (int mt = 0; mt < 2; mt++)
            #pragma unroll
            for (int tt = 0; tt < 4; tt++)
                #pragma unroll
                for (int e = 0; e < 4; e++) acc[mt][tt][e] = 0.0f;

        #pragma unroll
        for (int s = 0; s < 16; s++) {
            const uint32_t* bp = xb + s * 8;
            uint32_t a[2][4];                       // raw fp32 bits -> HW tf32 truncation
            #pragma unroll
            for (int mt = 0; mt < 2; mt++) {
                const uint32_t* mp = bp + mt * 16 * LDS_STRIDE;
                a[mt][0] = mp[0];
                a[mt][1] = mp[8 * LDS_STRIDE];
                a[mt][2] = mp[4];
                a[mt][3] = mp[8 * LDS_STRIDE + 4];
            }
            #pragma unroll
            for (int mt = 0; mt < 2; mt++)
                #pragma unroll
                for (int tt = 0; tt < 4; tt++) {
                    asm volatile(
                        "mma.sync.aligned.m16n8k8.row.col.f32.tf32.tf32.f32 "
                        "{%0,%1,%2,%3}, {%4,%5,%6,%7}, {%8,%9}, {%0,%1,%2,%3};"
                        : "+f"(acc[mt][tt][0]), "+f"(acc[mt][tt][1]),
                          "+f"(acc[mt][tt][2]), "+f"(acc[mt][tt][3])
                        : "r"(a[mt][0]), "r"(a[mt][1]), "r"(a[mt][2]), "r"(a[mt][3]),
                          "r"(Bf[s][tt][0]), "r"(Bf[s][tt][1]));
                }
        }

        // epilogue: 8B sector-aligned float2 stores
        #pragma unroll
        for (int mt = 0; mt < 2; mt++) {
            const int r1 = c * CHUNK + wm * 32 + mt * 16 + q;
            const int r2 = r1 + 8;
            #pragma unroll
            for (int tt = 0; tt < 4; tt++) {
                const int col = wo * 32 + tt * 8 + 2 * t;
                if (r1 < nrows)
                    *reinterpret_cast<float2*>(out + (size_t)r1 * O_DIM + col) =
                        make_float2(acc[mt][tt][0], acc[mt][tt][1]);
                if (r2 < nrows)
                    *reinterpret_cast<float2*>(out + (size_t)r2 * O_DIM + col) =
                        make_float2(acc[mt][tt][2], acc[mt][tt][3]);
            }
        }
    }
}

extern "C" void kernel_launch(void* const* d_in, const int* in_sizes, int n_in,
                              void* d_out, int out_size)
{
    const float* x = (const float*)d_in[0];
    const float* W = (const float*)d_in[1];
    float* out = (float*)d_out;

    const int nrows   = in_sizes[0] / K_DIM;
    const int nchunks = (nrows + CHUNK - 1) / CHUNK;

    cudaFuncSetAttribute(qlinear_tf32_kernel,
                         cudaFuncAttributeMaxDynamicSharedMemorySize, SMEM_BYTES);

    int sms = 148;
    cudaDeviceGetAttribute(&sms, cudaDevAttrMultiProcessorCount, 0);
    int grid = sms;
    if (grid > nchunks) grid = nchunks;
    if (grid < 1) grid = 1;

    qlinear_tf32_kernel<<<grid, THREADS, SMEM_BYTES>>>(x, W, out, nrows, nchunks);
}